// round 7
// baseline (speedup 1.0000x reference)
#include <cuda_runtime.h>
#include <math.h>

#define NV 20
#define NC 128
#define NT 64
#define NH 192
#define N_TL 9
#define N_LT 20
#define NDEPTH 3

// shared memory layout (floats)
#define OFF_SF   0        // 8192 : state f[64][128]
#define OFF_SY   8192     // 8192 : scratch y/z/h [64][128]
#define OFF_SG   16384    // 96
#define OFF_SRED 16480    // 16
#define OFF_SIDX 16496    // 64 ints
#define SMEM_FLOATS 16560
#define SMEM_BYTES (SMEM_FLOATS*4)

typedef unsigned long long u64;
union F2U { float2 f2; u64 u; float f[2]; };
union F4U { float4 v; u64 d[2]; float f[4]; };

struct Params {
  const float* x;
  const float* tl_table; const float* lane_table;
  const float* ch1w; const float* ch1b; const float* ch2w; const float* ch2b;
  const float* tk1w; const float* tk1b; const float* tk2w; const float* tk2b;
  const float* bn1w; const float* bn1b;
  const float* bt1w; const float* bt1b; const float* bt2w; const float* bt2b;
  const float* bn2w; const float* bn2b;
  const float* bc1w; const float* bc1b; const float* bc2w; const float* bc2b;
  const float* nw;  const float* nb;
  const float* e1w; const float* e1b; const float* e2w; const float* e2b;
  float* out; float* mask_out; float* pos_out;
};

__device__ __forceinline__ float gelu_f(float v){
  return 0.5f * v * (1.0f + erff(v * 0.70710678118654752440f));
}
__device__ __forceinline__ u64 rep2(float v){
  u64 r; asm("mov.b64 %0, {%1, %1};" : "=l"(r) : "f"(v)); return r;
}
__device__ __forceinline__ void ffma2(u64& d, u64 a, u64 b){
  asm("fma.rn.f32x2 %0, %1, %2, %0;" : "+l"(d) : "l"(a), "l"(b));
}

// ---------------- token-type GEMM (weights streamed from global) -------------
// out[u][c] = sum_{k<K} A[k][c] * W[k][u];  A natural [K][128] smem, W [K][64] gmem.
// f2 halves = u-pair: acc[p][j] = (out[warp*8+2p][c], out[warp*8+2p+1][c]), c=lane+32j
template<int K>
__device__ __forceinline__ void tok_gemm_g(const float* A, const float* __restrict__ Wg,
                                           u64 acc[4][4], int lane, int warp){
  const float* wp = Wg + warp*8;
  const float* ap = A + lane;
  #pragma unroll 4
  for (int k = 0; k < K; k++){
    F4U w0, w1;
    w0.v = *reinterpret_cast<const float4*>(wp + k*64);      // uniform LDG.128
    w1.v = *reinterpret_cast<const float4*>(wp + k*64 + 4);
    u64 a[4];
    #pragma unroll
    for (int j = 0; j < 4; j++) a[j] = rep2(ap[k*NC + 32*j]); // LDS.32 conflict-free
    u64 wp4[4] = { w0.d[0], w0.d[1], w1.d[0], w1.d[1] };
    #pragma unroll
    for (int p = 0; p < 4; p++)
      #pragma unroll
      for (int j = 0; j < 4; j++) ffma2(acc[p][j], wp4[p], a[j]);
  }
}

// ---------------- channel-type GEMM (weights streamed from global) -----------
// out[t][c] = sum_{k<128} A[t][k] * W[k][c]; A rows warp-local in smem (base As),
// W [128][128] gmem, coalesced LDG.128 (lane covers c-quad 4*lane..4*lane+3).
// acc[i][0] = (c=4l, 4l+1), acc[i][1] = (4l+2, 4l+3), t = row i of As.
template<int I>
__device__ __forceinline__ void chan_gemm_g(const float* As, const float* __restrict__ Wg,
                                            u64 acc[I][2], int lane){
  const float* wl = Wg + 4*lane;
  #pragma unroll 2
  for (int c4 = 0; c4 < 32; c4++){
    float4 a4[I];
    #pragma unroll
    for (int i = 0; i < I; i++)
      a4[i] = *reinterpret_cast<const float4*>(As + i*NC + 4*c4);   // LDS.128 bcast
    #pragma unroll
    for (int r = 0; r < 4; r++){
      F4U w; w.v = *reinterpret_cast<const float4*>(wl + (4*c4 + r)*NC);  // LDG.128
      #pragma unroll
      for (int i = 0; i < I; i++){
        float av = (r==0) ? a4[i].x : (r==1) ? a4[i].y : (r==2) ? a4[i].z : a4[i].w;
        u64 a = rep2(av);
        ffma2(acc[i][0], a, w.d[0]);
        ffma2(acc[i][1], a, w.d[1]);
      }
    }
  }
}

template<int A0, int A1>
__device__ __forceinline__ void zero_acc(u64 acc[A0][A1]){
  #pragma unroll
  for (int i = 0; i < A0; i++)
    #pragma unroll
    for (int j = 0; j < A1; j++) acc[i][j] = 0ull;
}

// LN of one row (128 ch, 4 per lane) read from src row, written to dst row
__device__ __forceinline__ void ln_row(const float* srow, float* drow,
                                       const float wg[4], const float bg[4], int lane){
  float v[4]; float s = 0.f, q = 0.f;
  #pragma unroll
  for (int j = 0; j < 4; j++){
    v[j] = srow[lane + 32*j];
    s += v[j]; q += v[j]*v[j];
  }
  #pragma unroll
  for (int o = 16; o > 0; o >>= 1){
    s += __shfl_xor_sync(0xffffffffu, s, o);
    q += __shfl_xor_sync(0xffffffffu, q, o);
  }
  float m  = s * (1.f/NC);
  float var = q * (1.f/NC) - m*m;
  float rs = rsqrtf(var + 1e-5f);
  #pragma unroll
  for (int j = 0; j < 4; j++)
    drow[lane + 32*j] = (v[j]-m)*rs*wg[j] + bg[j];
}

__global__ void __launch_bounds__(256, 2)
lane_fusion_kernel(Params P){
  extern __shared__ float smem[];
  float* sf  = smem + OFF_SF;
  float* sy  = smem + OFF_SY;
  float* sg  = smem + OFF_SG;
  float* sred= smem + OFF_SRED;
  int*   sidx= (int*)(smem + OFF_SIDX);

  const int tid  = threadIdx.x;
  const int lane = tid & 31;
  const int warp = tid >> 5;
  const int r    = blockIdx.x;
  const float* xr = P.x + (size_t)r * (NV*5);

  // ----- preprocess -----
  if (tid < NV){
    float x0 = xr[tid*5+0], x1 = xr[tid*5+1], hg = xr[tid*5+2];
    float x3 = xr[tid*5+3], x4 = xr[tid*5+4];
    float ch = cosf(hg), sh = sinf(hg);
    sg[tid*4+0] = x0; sg[tid*4+1] = x1; sg[tid*4+2] = ch; sg[tid*4+3] = sh;
    int tl = (int)x3; tl = tl < 0 ? 0 : (tl > N_TL-1 ? N_TL-1 : tl);
    int lt = (int)x4; lt = lt < 0 ? 0 : (lt > N_LT-1 ? N_LT-1 : lt);
    sidx[tid]      = tl;
    sidx[NV+tid]   = lt;
    sidx[2*NV+tid] = (x0==0.f && x1==0.f && ch==0.f && sh==0.f) ? 1 : 0;
  }
  if (tid < 5){
    float mid = xr[(NV/2)*5 + tid];
    float sc = (tid==3) ? (1.f/(N_TL-1)) : ((tid==4) ? (1.f/(N_LT-1)) : 1.f);
    P.pos_out[(size_t)r*5 + tid] = mid * sc;
  }
  __syncthreads();
  if (tid == 0){
    int mp = 1;
    for (int v = 0; v < NV; v++) mp &= sidx[2*NV+v];
    sidx[3*NV] = mp;
    P.mask_out[r] = mp ? 1.f : 0.f;
  }

  // ----- stage 1a: h1[v][c] = gelu(g @ ch1w + b) -> sy rows 0..19; 20..23 zero
  {
    int c  = tid & 127;
    int hf = tid >> 7;
    float w0 = P.ch1w[0*NC + c], w1 = P.ch1w[1*NC + c];
    float w2 = P.ch1w[2*NC + c], w3 = P.ch1w[3*NC + c];
    float b  = P.ch1b[c];
    #pragma unroll
    for (int v = hf*10; v < hf*10 + 10; v++){
      float a = b + sg[v*4+0]*w0 + sg[v*4+1]*w1 + sg[v*4+2]*w2 + sg[v*4+3]*w3;
      sy[v*NC + c] = gelu_f(a);
    }
    if (hf == 0){
      #pragma unroll
      for (int v = NV; v < 24; v++) sy[v*NC + c] = 0.f;
    }
  }
  __syncthreads();

  // ----- stage 1b: f0[v][c] = h1 @ ch2w + b + tables -> sf rows 0..19
  {
    u64 acc[3][2]; zero_acc<3,2>(acc);
    chan_gemm_g<3>(sy + warp*3*NC, P.ch2w, acc, lane);
    #pragma unroll
    for (int i = 0; i < 3; i++){
      int v = warp*3 + i;
      if (v < NV){
        int c0 = 4*lane;
        F4U b4;  b4.v  = *reinterpret_cast<const float4*>(P.ch2b + c0);
        F4U tl4; tl4.v = *reinterpret_cast<const float4*>(P.tl_table   + sidx[v]*NC    + c0);
        F4U lt4; lt4.v = *reinterpret_cast<const float4*>(P.lane_table + sidx[NV+v]*NC + c0);
        F2U a0; a0.u = acc[i][0];
        F2U a1; a1.u = acc[i][1];
        F4U o;
        o.f[0] = a0.f[0] + b4.f[0] + tl4.f[0] + lt4.f[0];
        o.f[1] = a0.f[1] + b4.f[1] + tl4.f[1] + lt4.f[1];
        o.f[2] = a1.f[0] + b4.f[2] + tl4.f[2] + lt4.f[2];
        o.f[3] = a1.f[1] + b4.f[3] + tl4.f[3] + lt4.f[3];
        *reinterpret_cast<float4*>(sf + v*NC + c0) = o.v;
      }
    }
  }
  __syncthreads();

  // ----- token expansion: 20 -> 64 -----
  {
    u64 acc[4][4]; zero_acc<4,4>(acc);
    tok_gemm_g<NV>(sf, P.tk1w, acc, lane, warp);     // reads sf; z goes to sy
    #pragma unroll
    for (int p = 0; p < 4; p++){
      int u0 = warp*8 + 2*p;
      float b0 = P.tk1b[u0], b1 = P.tk1b[u0+1];
      #pragma unroll
      for (int j = 0; j < 4; j++){
        int c = lane + 32*j;
        F2U t; t.u = acc[p][j];
        sy[u0*NC + c]     = gelu_f(t.f[0] + b0);
        sy[(u0+1)*NC + c] = gelu_f(t.f[1] + b1);
      }
    }
    __syncthreads();
    zero_acc<4,4>(acc);
    tok_gemm_g<NT>(sy, P.tk2w, acc, lane, warp);
    #pragma unroll
    for (int p = 0; p < 4; p++){
      int t0 = warp*8 + 2*p;
      float b0 = P.tk2b[t0], b1 = P.tk2b[t0+1];
      #pragma unroll
      for (int j = 0; j < 4; j++){
        int c = lane + 32*j;
        F2U t; t.u = acc[p][j];
        sf[t0*NC + c]     = t.f[0] + b0;
        sf[(t0+1)*NC + c] = t.f[1] + b1;
      }
    }
  }
  __syncthreads();   // all warps done reading sy(z) + sf ready

  // ----- mixer blocks -----
  for (int d = 0; d < NDEPTH; d++){
    // LN1: warp-local rows warp*8+i (sf rows written by this warp) -> sy
    {
      float wg[4], bg[4];
      #pragma unroll
      for (int j = 0; j < 4; j++){
        wg[j] = P.bn1w[d*NC + lane + 32*j];
        bg[j] = P.bn1b[d*NC + lane + 32*j];
      }
      #pragma unroll
      for (int i = 0; i < 8; i++){
        int t = warp*8 + i;
        ln_row(sf + t*NC, sy + t*NC, wg, bg, lane);
      }
    }
    __syncthreads();   // A: sy(y) complete for all warps

    // token mix 1
    {
      u64 acc[4][4]; zero_acc<4,4>(acc);
      tok_gemm_g<NT>(sy, P.bt1w + d*NT*NT, acc, lane, warp);
      __syncthreads(); // B: all done reading y before z overwrite
      #pragma unroll
      for (int p = 0; p < 4; p++){
        int u0 = warp*8 + 2*p;
        float b0 = P.bt1b[d*NT + u0], b1 = P.bt1b[d*NT + u0+1];
        #pragma unroll
        for (int j = 0; j < 4; j++){
          int c = lane + 32*j;
          F2U t; t.u = acc[p][j];
          sy[u0*NC + c]     = gelu_f(t.f[0] + b0);
          sy[(u0+1)*NC + c] = gelu_f(t.f[1] + b1);
        }
      }
      __syncthreads(); // C: z complete
      zero_acc<4,4>(acc);
      tok_gemm_g<NT>(sy, P.bt2w + d*NT*NT, acc, lane, warp);
      // residual (warp-local rows)
      #pragma unroll
      for (int p = 0; p < 4; p++){
        int t0 = warp*8 + 2*p;
        float b0 = P.bt2b[d*NT + t0], b1 = P.bt2b[d*NT + t0+1];
        #pragma unroll
        for (int j = 0; j < 4; j++){
          int c = lane + 32*j;
          F2U t; t.u = acc[p][j];
          sf[t0*NC + c]     += t.f[0] + b0;
          sf[(t0+1)*NC + c] += t.f[1] + b1;
        }
      }
    }
    __syncthreads();   // D: all done reading z; sy free for LN2

    // LN2 -> sy (warp-local rows)
    {
      float wg[4], bg[4];
      #pragma unroll
      for (int j = 0; j < 4; j++){
        wg[j] = P.bn2w[d*NC + lane + 32*j];
        bg[j] = P.bn2b[d*NC + lane + 32*j];
      }
      #pragma unroll
      for (int i = 0; i < 8; i++){
        int t = warp*8 + i;
        ln_row(sf + t*NC, sy + t*NC, wg, bg, lane);
      }
    }
    __syncwarp();

    // channel mix C1: h = gelu(y2 @ Wc1 + b1) — warp-local rows, weights via LDG
    {
      u64 acc[8][2]; zero_acc<8,2>(acc);
      chan_gemm_g<8>(sy + warp*8*NC, P.bc1w + d*NC*NC, acc, lane);
      F4U b4; b4.v = *reinterpret_cast<const float4*>(P.bc1b + d*NC + 4*lane);
      #pragma unroll
      for (int i = 0; i < 8; i++){
        int t = warp*8 + i;
        F2U a0; a0.u = acc[i][0];
        F2U a1; a1.u = acc[i][1];
        F4U o;
        o.f[0] = gelu_f(a0.f[0] + b4.f[0]);
        o.f[1] = gelu_f(a0.f[1] + b4.f[1]);
        o.f[2] = gelu_f(a1.f[0] + b4.f[2]);
        o.f[3] = gelu_f(a1.f[1] + b4.f[3]);
        *reinterpret_cast<float4*>(sy + t*NC + 4*lane) = o.v;
      }
    }
    __syncwarp();

    // channel mix C2: f += h @ Wc2 + b2 — warp-local rows
    {
      u64 acc[8][2]; zero_acc<8,2>(acc);
      chan_gemm_g<8>(sy + warp*8*NC, P.bc2w + d*NC*NC, acc, lane);
      F4U b4; b4.v = *reinterpret_cast<const float4*>(P.bc2b + d*NC + 4*lane);
      #pragma unroll
      for (int i = 0; i < 8; i++){
        int t = warp*8 + i;
        F2U a0; a0.u = acc[i][0];
        F2U a1; a1.u = acc[i][1];
        F4U o; o.v = *reinterpret_cast<const float4*>(sf + t*NC + 4*lane);
        o.f[0] += a0.f[0] + b4.f[0];
        o.f[1] += a0.f[1] + b4.f[1];
        o.f[2] += a1.f[0] + b4.f[2];
        o.f[3] += a1.f[1] + b4.f[3];
        *reinterpret_cast<float4*>(sf + t*NC + 4*lane) = o.v;
      }
    }
    __syncwarp();
    // next LN1 reads sf warp-local rows; no block sync needed inside loop
  }
  __syncthreads();   // E: sf complete for mean

  // ----- epilogue: token mean, LN, emb MLP -----
  {
    int c  = tid & 127;
    int hf = tid >> 7;
    float ps = 0.f;
    #pragma unroll 8
    for (int t = hf*32; t < hf*32 + 32; t++) ps += sf[t*NC + c];
    sy[hf*128 + c] = ps;
  }
  __syncthreads();
  float fm = 0.f;
  if (tid < NC){
    fm = (sy[tid] + sy[128 + tid]) * (1.f/NT);
    float s = fm, q = fm*fm;
    #pragma unroll
    for (int o = 16; o > 0; o >>= 1){
      s += __shfl_xor_sync(0xffffffffu, s, o);
      q += __shfl_xor_sync(0xffffffffu, q, o);
    }
    if (lane == 0){ sred[warp] = s; sred[4+warp] = q; }
  }
  __syncthreads();
  if (tid < NC){
    float s = sred[0]+sred[1]+sred[2]+sred[3];
    float q = sred[4]+sred[5]+sred[6]+sred[7];
    float m  = s * (1.f/NC);
    float var = q * (1.f/NC) - m*m;
    float rs = rsqrtf(var + 1e-5f);
    sy[256 + tid] = (fm - m)*rs*P.nw[tid] + P.nb[tid];
  }
  __syncthreads();
  if (tid < NH){
    float a = P.e1b[tid];
    #pragma unroll 8
    for (int c = 0; c < NC; c++) a += sy[256 + c] * P.e1w[c*NH + tid];
    sy[512 + tid] = gelu_f(a);
  }
  __syncthreads();
  if (tid < NH){
    float o = P.e2b[tid];
    #pragma unroll 8
    for (int j = 0; j < NH; j++) o += sy[512 + j] * P.e2w[j*NH + tid];
    float valid = sidx[3*NV] ? 0.f : 1.f;
    P.out[(size_t)r * NH + tid] = o * valid;
  }
}

extern "C" void kernel_launch(void* const* d_in, const int* in_sizes, int n_in,
                              void* d_out, int out_size){
  (void)in_sizes; (void)n_in; (void)out_size;
  Params P;
  P.x         = (const float*)d_in[0];
  P.tl_table  = (const float*)d_in[1];
  P.lane_table= (const float*)d_in[2];
  P.ch1w = (const float*)d_in[3];  P.ch1b = (const float*)d_in[4];
  P.ch2w = (const float*)d_in[5];  P.ch2b = (const float*)d_in[6];
  P.tk1w = (const float*)d_in[7];  P.tk1b = (const float*)d_in[8];
  P.tk2w = (const float*)d_in[9];  P.tk2b = (const float*)d_in[10];
  P.bn1w = (const float*)d_in[11]; P.bn1b = (const float*)d_in[12];
  P.bt1w = (const float*)d_in[13]; P.bt1b = (const float*)d_in[14];
  P.bt2w = (const float*)d_in[15]; P.bt2b = (const float*)d_in[16];
  P.bn2w = (const float*)d_in[17]; P.bn2b = (const float*)d_in[18];
  P.bc1w = (const float*)d_in[19]; P.bc1b = (const float*)d_in[20];
  P.bc2w = (const float*)d_in[21]; P.bc2b = (const float*)d_in[22];
  P.nw   = (const float*)d_in[23]; P.nb   = (const float*)d_in[24];
  P.e1w  = (const float*)d_in[25]; P.e1b  = (const float*)d_in[26];
  P.e2w  = (const float*)d_in[27]; P.e2b  = (const float*)d_in[28];

  const int NRows = 8192;
  float* ob = (float*)d_out;
  P.out      = ob;
  P.mask_out = ob + (size_t)NRows*NH;
  P.pos_out  = ob + (size_t)NRows*NH + NRows;

  cudaFuncSetAttribute(lane_fusion_kernel,
                       cudaFuncAttributeMaxDynamicSharedMemorySize, SMEM_BYTES);
  lane_fusion_kernel<<<NRows, 256, SMEM_BYTES>>>(P);
}